// round 3
// baseline (speedup 1.0000x reference)
#include <cuda_runtime.h>
#include <cstddef>

// JPEG 8x8 blockify + orthonormal 2D DCT-II + quality-factor quantization.
// image: [16,1,1024,1024] f32, quality_factor: [16] f32
// out:   [16,64,128,128] f32, channel c = k*8 + l (k = row-freq, l = col-freq)
//
// One thread per 8x8 block. Memory-bound design:
//  - loads: 16x LDG.128 per thread, front-batched (high MLP)
//  - DCT: even/odd butterfly, coefficients as FFMA immediates
//  - stores: 64x STG.32, perfectly coalesced per frequency plane
//  - quant scale: per-CTA shared (CTA never spans batch items)

#define A0 0.35355339059327373f  // 1/sqrt(8)
#define H1 0.49039264020161522f  // cos(1*pi/16)/2
#define H2 0.46193976625564337f  // cos(2*pi/16)/2
#define H3 0.41573480615127262f  // cos(3*pi/16)/2
#define H4 0.35355339059327376f  // cos(4*pi/16)/2
#define H5 0.27778511650980111f  // cos(5*pi/16)/2
#define H6 0.19134171618254489f  // cos(6*pi/16)/2
#define H7 0.09754516100806413f  // cos(7*pi/16)/2

__constant__ int c_qtab[64] = {
    16, 11, 10, 16, 24, 40, 51, 61,
    12, 12, 14, 19, 26, 58, 60, 55,
    14, 13, 16, 24, 40, 57, 69, 56,
    14, 17, 22, 29, 51, 87, 80, 62,
    18, 22, 37, 56, 68, 109, 103, 77,
    24, 36, 55, 64, 81, 104, 113, 92,
    49, 64, 78, 87, 103, 121, 120, 101,
    72, 92, 95, 98, 112, 100, 103, 99};

__device__ __forceinline__ void dct8(float& x0, float& x1, float& x2, float& x3,
                                     float& x4, float& x5, float& x6, float& x7) {
    float e0 = x0 + x7, e1 = x1 + x6, e2 = x2 + x5, e3 = x3 + x4;
    float o0 = x0 - x7, o1 = x1 - x6, o2 = x2 - x5, o3 = x3 - x4;
    float ee0 = e0 + e3, ee1 = e1 + e2;
    float eo0 = e0 - e3, eo1 = e1 - e2;
    x0 = A0 * (ee0 + ee1);
    x4 = H4 * (ee0 - ee1);
    x2 = H2 * eo0 + H6 * eo1;
    x6 = H6 * eo0 - H2 * eo1;
    x1 = H1 * o0 + H3 * o1 + H5 * o2 + H7 * o3;
    x3 = H3 * o0 - H7 * o1 - H1 * o2 - H5 * o3;
    x5 = H5 * o0 - H1 * o1 + H7 * o2 + H3 * o3;
    x7 = H7 * o0 - H5 * o1 + H3 * o2 - H1 * o3;
}

__global__ __launch_bounds__(256) void jpeg_dct_kernel(
    const float* __restrict__ img,
    const float* __restrict__ qf,
    float* __restrict__ out) {
    __shared__ float sScale[64];

    int tid = blockIdx.x * 256 + threadIdx.x;
    int b = tid >> 14;          // 16384 blocks per image, CTA never spans b

    if (threadIdx.x < 64) {
        float q = qf[b];
        float factor = (q < 50.0f) ? (5000.0f / q) : (200.0f - 2.0f * q);
        sScale[threadIdx.x] = 100.0f / ((float)c_qtab[threadIdx.x] * factor);
    }
    __syncthreads();

    int hb = (tid >> 7) & 127;
    int wb = tid & 127;

    const float* p = img + ((size_t)b << 20) + (size_t)(hb * 8) * 1024 + wb * 8;

    float x[8][8];
#pragma unroll
    for (int r = 0; r < 8; r++) {
        float4 v0 = *(const float4*)(p + (size_t)r * 1024);
        float4 v1 = *(const float4*)(p + (size_t)r * 1024 + 4);
        x[r][0] = v0.x - 128.0f;
        x[r][1] = v0.y - 128.0f;
        x[r][2] = v0.z - 128.0f;
        x[r][3] = v0.w - 128.0f;
        x[r][4] = v1.x - 128.0f;
        x[r][5] = v1.y - 128.0f;
        x[r][6] = v1.z - 128.0f;
        x[r][7] = v1.w - 128.0f;
    }

    // Column transform (contract over intra-block row index)
#pragma unroll
    for (int c = 0; c < 8; c++) {
        dct8(x[0][c], x[1][c], x[2][c], x[3][c],
             x[4][c], x[5][c], x[6][c], x[7][c]);
    }
    // Row transform (contract over intra-block column index)
#pragma unroll
    for (int k = 0; k < 8; k++) {
        dct8(x[k][0], x[k][1], x[k][2], x[k][3],
             x[k][4], x[k][5], x[k][6], x[k][7]);
    }

    // out[b][c][hb][wb]; per-image block = 64*128*128 = 2^20
    float* o = out + ((size_t)b << 20) + hb * 128 + wb;
#pragma unroll
    for (int i = 0; i < 64; i++) {
        o[(size_t)i * 16384] = x[i >> 3][i & 7] * sScale[i];
    }
}

extern "C" void kernel_launch(void* const* d_in, const int* in_sizes, int n_in,
                              void* d_out, int out_size) {
    const float* img = (const float*)d_in[0];
    const float* qf = (const float*)d_in[1];
    float* out = (float*)d_out;
    // 16 images * 128*128 blocks = 262144 threads
    jpeg_dct_kernel<<<1024, 256>>>(img, qf, out);
}

// round 5
// speedup vs baseline: 1.0220x; 1.0220x over previous
#include <cuda_runtime.h>
#include <cstddef>

// JPEG 8x8 blockify + orthonormal 2D DCT-II + QF quantization.
// image: [16,1,1024,1024] f32, qf: [16] f32 -> out [16,64,128,128] f32.
//
// R4: two threads (a lane pair) per 8x8 block. Each thread owns 4 columns
// (x[8][4] = 32 regs), column DCT is thread-local, row DCT exchanges the
// halves via 4x SHFL.BFLY per k-row and uses per-thread coefficient
// registers (selected once from the half index) so both halves run the
// identical instruction stream. __launch_bounds__(256,4) -> <=64 regs,
// 4 CTAs/SM resident (vs 3 at 80 regs in R1) to keep DRAM continuously fed.

#define A0 0.35355339059327373f  // 1/sqrt(8)
#define H1 0.49039264020161522f  // cos(1*pi/16)/2
#define H2 0.46193976625564337f  // cos(2*pi/16)/2
#define H3 0.41573480615127262f  // cos(3*pi/16)/2
#define H4 0.35355339059327376f  // cos(4*pi/16)/2
#define H5 0.27778511650980111f  // cos(5*pi/16)/2
#define H6 0.19134171618254489f  // cos(6*pi/16)/2
#define H7 0.09754516100806413f  // cos(7*pi/16)/2

__constant__ float c_qtab[64] = {
    16.f, 11.f, 10.f, 16.f, 24.f, 40.f, 51.f, 61.f,
    12.f, 12.f, 14.f, 19.f, 26.f, 58.f, 60.f, 55.f,
    14.f, 13.f, 16.f, 24.f, 40.f, 57.f, 69.f, 56.f,
    14.f, 17.f, 22.f, 29.f, 51.f, 87.f, 80.f, 62.f,
    18.f, 22.f, 37.f, 56.f, 68.f, 109.f, 103.f, 77.f,
    24.f, 36.f, 55.f, 64.f, 81.f, 104.f, 113.f, 92.f,
    49.f, 64.f, 78.f, 87.f, 103.f, 121.f, 120.f, 101.f,
    72.f, 92.f, 95.f, 98.f, 112.f, 100.f, 103.f, 99.f};

__device__ __forceinline__ void dct8(float& x0, float& x1, float& x2, float& x3,
                                     float& x4, float& x5, float& x6, float& x7) {
    float e0 = x0 + x7, e1 = x1 + x6, e2 = x2 + x5, e3 = x3 + x4;
    float o0 = x0 - x7, o1 = x1 - x6, o2 = x2 - x5, o3 = x3 - x4;
    float ee0 = e0 + e3, ee1 = e1 + e2;
    float eo0 = e0 - e3, eo1 = e1 - e2;
    x0 = A0 * (ee0 + ee1);
    x4 = H4 * (ee0 - ee1);
    x2 = H2 * eo0 + H6 * eo1;
    x6 = H6 * eo0 - H2 * eo1;
    x1 = H1 * o0 + H3 * o1 + H5 * o2 + H7 * o3;
    x3 = H3 * o0 - H7 * o1 - H1 * o2 - H5 * o3;
    x5 = H5 * o0 - H1 * o1 + H7 * o2 + H3 * o3;
    x7 = H7 * o0 - H5 * o1 + H3 * o2 - H1 * o3;
}

__global__ __launch_bounds__(256, 4) void jpeg_dct_kernel(
    const float* __restrict__ img,
    const float* __restrict__ qf,
    float* __restrict__ out) {
    __shared__ __align__(16) float sScale[64];

    int tid = blockIdx.x * 256 + threadIdx.x;
    int b = tid >> 15;  // 2 threads/block, 32768 threads per image; CTA-uniform

    if (threadIdx.x < 64) {
        float q = qf[b];
        float factor = (q < 50.0f) ? (5000.0f / q) : (200.0f - 2.0f * q);
        sScale[threadIdx.x] = 100.0f / (c_qtab[threadIdx.x] * factor);
    }
    __syncthreads();

    int bid = tid >> 1;      // 8x8 block index
    int h = tid & 1;         // half: columns 4h..4h+3
    int hb = (bid >> 7) & 127;
    int wb = bid & 127;

    // Loads: lane pair covers 32B; warp covers 512B contiguous per row.
    const float* p = img + ((size_t)b << 20) + (size_t)hb * 8192 + wb * 8 + h * 4;

    float x[8][4];
#pragma unroll
    for (int r = 0; r < 8; r++) {
        float4 v = *(const float4*)(p + (size_t)r * 1024);
        x[r][0] = v.x - 128.0f;
        x[r][1] = v.y - 128.0f;
        x[r][2] = v.z - 128.0f;
        x[r][3] = v.w - 128.0f;
    }

    // Column transform: thread-local, 4 columns.
#pragma unroll
    for (int c = 0; c < 4; c++) {
        dct8(x[0][c], x[1][c], x[2][c], x[3][c],
             x[4][c], x[5][c], x[6][c], x[7][c]);
    }

    // Per-half row-transform coefficients (selected once; both halves then
    // execute the identical arithmetic on s/d):
    //   h=0 emits l = 0,1,2,3 ; h=1 emits l = 4,5,6,7
    bool hi = (h != 0);
    float cA0 = hi ?  H4 :  A0, cA1 = hi ? -H4 :  A0;   // l0 / l4
    float cB0 = hi ? -H6 :  H2, cB1 = hi ?  H2 :  H6;   // l2 / l6
    float cC0 = hi ? -H3 :  H1, cC1 = hi ? -H7 :  H3,   // l1 / l5
          cC2 = hi ?  H1 :  H5, cC3 = hi ? -H5 :  H7;
    float cD0 = hi ?  H1 :  H3, cD1 = hi ? -H3 : -H7,   // l3 / l7
          cD2 = hi ?  H5 : -H1, cD3 = hi ? -H7 : -H5;

    float* ob = out + ((size_t)b << 20) + hb * 128 + wb + (size_t)(h * 4) * 16384;

#pragma unroll
    for (int k = 0; k < 8; k++) {
        float v0 = x[k][0], v1 = x[k][1], v2 = x[k][2], v3 = x[k][3];
        float p0 = __shfl_xor_sync(0xffffffffu, v0, 1);
        float p1 = __shfl_xor_sync(0xffffffffu, v1, 1);
        float p2 = __shfl_xor_sync(0xffffffffu, v2, 1);
        float p3 = __shfl_xor_sync(0xffffffffu, v3, 1);
        // s_i = e_i (h=0) / e_{3-i} (h=1);  d_i = o_i (h=0) / -o_{3-i} (h=1)
        float s0 = v0 + p3, s1 = v1 + p2, s2 = v2 + p1, s3 = v3 + p0;
        float d0 = v0 - p3, d1 = v1 - p2, d2 = v2 - p1, d3 = v3 - p0;
        float ee0 = s0 + s3, ee1 = s1 + s2;
        float u0 = s0 - s3, u1 = s1 - s2;

        float oA = cA0 * ee0 + cA1 * ee1;                              // l = 4h+0
        float oB = cB0 * u0 + cB1 * u1;                                // l = 4h+2
        float oC = cC0 * d0 + cC1 * d1 + cC2 * d2 + cC3 * d3;          // l = 4h+1
        float oD = cD0 * d0 + cD1 * d1 + cD2 * d2 + cD3 * d3;          // l = 4h+3

        float4 sc = *(const float4*)&sScale[k * 8 + 4 * h];
        float* ok = ob + (size_t)(k * 8) * 16384;
        ok[0]                  = oA * sc.x;
        ok[(size_t)1 * 16384]  = oC * sc.y;
        ok[(size_t)2 * 16384]  = oB * sc.z;
        ok[(size_t)3 * 16384]  = oD * sc.w;
    }
}

extern "C" void kernel_launch(void* const* d_in, const int* in_sizes, int n_in,
                              void* d_out, int out_size) {
    const float* img = (const float*)d_in[0];
    const float* qf = (const float*)d_in[1];
    float* out = (float*)d_out;
    // 16 images * 16384 blocks * 2 threads = 524288 threads -> 2048 CTAs
    jpeg_dct_kernel<<<2048, 256>>>(img, qf, out);
}